// round 4
// baseline (speedup 1.0000x reference)
#include <cuda_runtime.h>

#define N_NODES 100000
#define N_EDGES 3200000
#define N_FEAT  512
#define N_HID   16
#define N_CLS   7

// Scratch (device globals; no allocation allowed). 128B-aligned for float4 /
// red.global.add.v4.f32 (needs >=16B).
__device__ __align__(128) float g_h   [N_NODES * N_HID];   // x @ W1
__device__ __align__(128) float g_agg1[N_NODES * N_HID];   // segment_sum of g_h
__device__ __align__(128) float g_h2  [N_NODES * 8];       // relu(agg1+b1) @ W2, padded to 8
__device__ __align__(128) float g_agg2[N_NODES * 8];       // segment_sum of g_h2

typedef unsigned long long u64;

__device__ __forceinline__ u64 pack2(float a, float b) {
    u64 r; asm("mov.b64 %0, {%1,%2};" : "=l"(r) : "f"(a), "f"(b)); return r;
}
__device__ __forceinline__ void unpack2(u64 v, float& a, float& b) {
    asm("mov.b64 {%0,%1}, %2;" : "=f"(a), "=f"(b) : "l"(v));
}
__device__ __forceinline__ void ffma2(u64& d, u64 a, u64 b) {
    asm("fma.rn.f32x2 %0, %1, %2, %0;" : "+l"(d) : "l"(a), "l"(b));
}
__device__ __forceinline__ void fadd2(u64& d, u64 a) {
    asm("add.rn.f32x2 %0, %0, %1;" : "+l"(d) : "l"(a));
}
__device__ __forceinline__ void red4(float* p, float4 v) {
    asm volatile("red.global.add.v4.f32 [%0], {%1,%2,%3,%4};"
                 :: "l"(p), "f"(v.x), "f"(v.y), "f"(v.z), "f"(v.w) : "memory");
}

// ---------------------------------------------------------------- init aggs
__global__ void init_kernel() {
    int stride = gridDim.x * blockDim.x;
    int i = blockIdx.x * blockDim.x + threadIdx.x;
    float4 z = make_float4(0.f, 0.f, 0.f, 0.f);
    const int n1 = N_NODES * N_HID / 4;
    const int n2 = N_NODES * 8 / 4;
    for (int j = i; j < n1; j += stride) reinterpret_cast<float4*>(g_agg1)[j] = z;
    for (int j = i; j < n2; j += stride) reinterpret_cast<float4*>(g_agg2)[j] = z;
}

// ---------------------------------------------------------------- GEMM1: h = x @ W1
// Block: 256 thr = 8 warps. Warp w: column-quad q = w&3 (cols 4q..4q+3),
// row slot s = w>>2 (2 rows staged per iteration).
// Lane l: k-range [16l, 16l+16), W held in registers as 32 packed f32x2.
__global__ void __launch_bounds__(256, 2)
gemm1_kernel(const float* __restrict__ x, const float* __restrict__ W1) {
    __shared__ float4 xs[256];   // 2 rows * 512 floats, XOR-swizzled
    const int tid = threadIdx.x;
    const int w = tid >> 5, l = tid & 31;
    const int q = w & 3, s = w >> 2;

    u64 wr0[16], wr1[16];
#pragma unroll
    for (int j = 0; j < 16; j++) {
        float4 wv = *reinterpret_cast<const float4*>(W1 + (l * 16 + j) * 16 + q * 4);
        wr0[j] = pack2(wv.x, wv.y);
        wr1[j] = pack2(wv.z, wv.w);
    }

    float4* h4 = reinterpret_cast<float4*>(g_h);
    const int swz_t = tid ^ ((tid >> 3) & 7);
    const int g0 = s * 128 + l * 4;   // granule base (float4 units) for this thread's k-range

    for (int p = blockIdx.x; p < N_NODES / 2; p += gridDim.x) {
        // stage 2 contiguous rows (coalesced float4)
        float4 v = reinterpret_cast<const float4*>(x)[(size_t)p * 256 + tid];
        __syncthreads();          // prior-iteration readers done
        xs[swz_t] = v;
        __syncthreads();

        u64 a0 = 0ull, a1 = 0ull; // two packed-f32x2 accumulators (4 columns)
#pragma unroll
        for (int i = 0; i < 4; i++) {
            int g = g0 + i;
            float4 xv = xs[g ^ ((g >> 3) & 7)];
            u64 xx;
            xx = pack2(xv.x, xv.x); ffma2(a0, xx, wr0[4*i+0]); ffma2(a1, xx, wr1[4*i+0]);
            xx = pack2(xv.y, xv.y); ffma2(a0, xx, wr0[4*i+1]); ffma2(a1, xx, wr1[4*i+1]);
            xx = pack2(xv.z, xv.z); ffma2(a0, xx, wr0[4*i+2]); ffma2(a1, xx, wr1[4*i+2]);
            xx = pack2(xv.w, xv.w); ffma2(a0, xx, wr0[4*i+3]); ffma2(a1, xx, wr1[4*i+3]);
        }
#pragma unroll
        for (int off = 16; off; off >>= 1) {
            u64 t0 = __shfl_down_sync(0xffffffffu, a0, off);
            u64 t1 = __shfl_down_sync(0xffffffffu, a1, off);
            fadd2(a0, t0); fadd2(a1, t1);
        }
        if (l == 0) {
            float4 o;
            unpack2(a0, o.x, o.y);
            unpack2(a1, o.z, o.w);
            h4[(2 * p + s) * 4 + q] = o;
        }
    }
}

// ---------------------------------------------------------------- scatter: agg1 += h[src] at dst
// edge_index arrives as int32 (harness supports float32/int32/bf16 only;
// the reference's int64 is materialized as int32).
__global__ void scatter16_kernel(const int* __restrict__ ei) {
    int e = blockIdx.x * blockDim.x + threadIdx.x;
    if (e >= N_EDGES) return;
    int sidx = ei[e];
    int didx = ei[N_EDGES + e];
    const float4* hp = reinterpret_cast<const float4*>(g_h) + sidx * 4;
    float4 v0 = hp[0], v1 = hp[1], v2 = hp[2], v3 = hp[3];
    float* ap = g_agg1 + didx * 16;
    red4(ap,      v0);
    red4(ap + 4,  v1);
    red4(ap + 8,  v2);
    red4(ap + 12, v3);
}

// ---------------------------------------------------------------- h2 = relu(agg1+b1) @ W2 (padded to 8)
__global__ void transform2_kernel(const float* __restrict__ W2, const float* __restrict__ b1) {
    __shared__ float Ws[16 * 7];
    __shared__ float bs[16];
    int tid = threadIdx.x;
    if (tid < 112) Ws[tid] = W2[tid];
    if (tid < 16)  bs[tid] = b1[tid];
    __syncthreads();

    int stride = gridDim.x * blockDim.x;
    for (int n = blockIdx.x * blockDim.x + tid; n < N_NODES; n += stride) {
        const float4* ap = reinterpret_cast<const float4*>(g_agg1) + n * 4;
        float hr[16];
#pragma unroll
        for (int i = 0; i < 4; i++) {
            float4 t = ap[i];
            hr[4*i+0] = t.x; hr[4*i+1] = t.y; hr[4*i+2] = t.z; hr[4*i+3] = t.w;
        }
#pragma unroll
        for (int k = 0; k < 16; k++) hr[k] = fmaxf(hr[k] + bs[k], 0.f);

        float o[8];
        o[7] = 0.f;
#pragma unroll
        for (int c = 0; c < 7; c++) {
            float acc = 0.f;
#pragma unroll
            for (int k = 0; k < 16; k++) acc = fmaf(hr[k], Ws[k * 7 + c], acc);
            o[c] = acc;
        }
        float4* op = reinterpret_cast<float4*>(g_h2) + n * 2;
        op[0] = make_float4(o[0], o[1], o[2], o[3]);
        op[1] = make_float4(o[4], o[5], o[6], o[7]);
    }
}

// ---------------------------------------------------------------- scatter: agg2 += h2[src] at dst
__global__ void scatter8_kernel(const int* __restrict__ ei) {
    int e = blockIdx.x * blockDim.x + threadIdx.x;
    if (e >= N_EDGES) return;
    int sidx = ei[e];
    int didx = ei[N_EDGES + e];
    const float4* hp = reinterpret_cast<const float4*>(g_h2) + sidx * 2;
    float4 v0 = hp[0], v1 = hp[1];
    float* ap = g_agg2 + didx * 8;
    red4(ap,     v0);
    red4(ap + 4, v1);
}

// ---------------------------------------------------------------- out = log_softmax(agg2 + b2)
__global__ void logsoftmax_kernel(const float* __restrict__ b2, float* __restrict__ out) {
    int stride = gridDim.x * blockDim.x;
    for (int n = blockIdx.x * blockDim.x + threadIdx.x; n < N_NODES; n += stride) {
        const float4* ap = reinterpret_cast<const float4*>(g_agg2) + n * 2;
        float4 a = ap[0], b = ap[1];
        float v[7];
        v[0] = a.x + __ldg(b2 + 0);
        v[1] = a.y + __ldg(b2 + 1);
        v[2] = a.z + __ldg(b2 + 2);
        v[3] = a.w + __ldg(b2 + 3);
        v[4] = b.x + __ldg(b2 + 4);
        v[5] = b.y + __ldg(b2 + 5);
        v[6] = b.z + __ldg(b2 + 6);
        float m = v[0];
#pragma unroll
        for (int c = 1; c < 7; c++) m = fmaxf(m, v[c]);
        float ssum = 0.f;
#pragma unroll
        for (int c = 0; c < 7; c++) ssum += expf(v[c] - m);
        float lse = m + logf(ssum);
#pragma unroll
        for (int c = 0; c < 7; c++) out[n * 7 + c] = v[c] - lse;
    }
}

// ----------------------------------------------------------------
// Identify inputs by element count (all pairwise distinct):
//   x: 51,200,000   edge_index: 6,400,000   W1: 8,192   W2: 112   b1: 16   b2: 7
extern "C" void kernel_launch(void* const* d_in, const int* in_sizes, int n_in,
                              void* d_out, int out_size) {
    const float* x  = nullptr;
    const int*   ei = nullptr;
    const float* W1 = nullptr;
    const float* b1 = nullptr;
    const float* W2 = nullptr;
    const float* b2 = nullptr;

    for (int i = 0; i < n_in; i++) {
        switch (in_sizes[i]) {
            case N_NODES * N_FEAT: x  = (const float*)d_in[i]; break;
            case 2 * N_EDGES:      ei = (const int*)d_in[i];   break;
            case N_FEAT * N_HID:   W1 = (const float*)d_in[i]; break;
            case N_HID:            b1 = (const float*)d_in[i]; break;
            case N_HID * N_CLS:    W2 = (const float*)d_in[i]; break;
            case N_CLS:            b2 = (const float*)d_in[i]; break;
            default: break;
        }
    }
    float* out = (float*)d_out;

    init_kernel<<<592, 256>>>();
    gemm1_kernel<<<296, 256>>>(x, W1);
    scatter16_kernel<<<N_EDGES / 256, 256>>>(ei);
    transform2_kernel<<<592, 256>>>(W2, b1);
    scatter8_kernel<<<N_EDGES / 256, 256>>>(ei);
    logsoftmax_kernel<<<592, 256>>>(b2, out);
}